// round 14
// baseline (speedup 1.0000x reference)
#include <cuda_runtime.h>
#include <cstdint>

#define N_PTS 16384
#define M_PTS 4096
#define KNN_K 16
#define EMB   64
#define NEDGE (N_PTS*KNN_K)   // 262144
#define FLT_MAX_C 3.402823466e+38f

#define GRID_C 8              // 8x8x8 = 512 cells
#define NCELL  (GRID_C*GRID_C*GRID_C)

// ---------------- device scratch (static globals: allocation-free) ----------
__device__ int      g_idx[M_PTS];
__device__ float4   g_ps[M_PTS];          // sampled pos: x,y,z, sumsq
__device__ float    g_xs[M_PTS*EMB];      // gathered features
__device__ float    g_delta[M_PTS*3];     // h-MLP output per sampled point
__device__ float    g_u[N_PTS*EMB];       // x @ f_w1[3:,:] + f_b1  (pre-ReLU)
__device__ float    g_sn[N_PTS];          // ||pos||^2 per point
__device__ int      g_nbr[NEDGE];         // knn neighbor ids
__device__ float    g_hidden[NEDGE*EMB];  // per-edge layer-1 post-ReLU
__device__ unsigned g_aggr[M_PTS*EMB];    // encoded float max accumulators

// spatial-sort scratch for FPS  (g_cnt zero-initialized at load; scan_kernel
// re-zeroes it after use so every graph replay sees a clean histogram)
__device__ int            g_cnt[NCELL];
__device__ int            g_cur[NCELL];
__device__ int            g_cell[N_PTS];
__device__ float          g_rx[N_PTS], g_ry[N_PTS], g_rz[N_PTS];  // sorted coords
__device__ unsigned short g_rid16[N_PTS]; // sorted order -> original index

// order-preserving float<->uint encoding for atomicMax
__device__ __forceinline__ unsigned encf(float f) {
    unsigned u = __float_as_uint(f);
    return (u & 0x80000000u) ? ~u : (u | 0x80000000u);
}
__device__ __forceinline__ float decf(unsigned u) {
    return (u & 0x80000000u) ? __uint_as_float(u & 0x7FFFFFFFu) : __uint_as_float(~u);
}

// u64 max via shuffle butterfly (all lanes end with the max)
__device__ __forceinline__ unsigned long long shflmax64(unsigned long long k) {
#pragma unroll
    for (int o = 16; o; o >>= 1) {
        unsigned long long k2 = __shfl_xor_sync(0xFFFFFFFFu, k, o);
        k = (k2 > k) ? k2 : k;
    }
    return k;
}

// packed f32x2 ops (two independent IEEE-rn fp32 ops per instruction; each
// half rounds bit-identically to the scalar op)
#define SUB2(out, a, b) asm("sub.rn.f32x2 %0, %1, %2;" : "=l"(out) : "l"(a), "l"(b))
#define MUL2(out, a, b) asm("mul.rn.f32x2 %0, %1, %2;" : "=l"(out) : "l"(a), "l"(b))
#define ADD2(out, a, b) asm("add.rn.f32x2 %0, %1, %2;" : "=l"(out) : "l"(a), "l"(b))
#define PACK2(out, lo, hi) asm("mov.b64 %0, {%1, %2};" : "=l"(out) : "r"(lo), "r"(hi))
#define UNPACK2(lo, hi, in) asm("mov.b64 {%0, %1}, %2;" : "=r"(lo), "=r"(hi) : "l"(in))

// paired smem layout: sorted point s lives at float-addr
//   2*(s>>4) + ((s>>1)&7)*2048 + (s&1)
// so thread t's pair p (points 16t+2p, 16t+2p+1) is ONE u64 at index t+p*1024
// (lane-consecutive -> conflict-free LDS.64).
__device__ __forceinline__ int phys_f32(int s) {
    return ((s >> 4) << 1) + (((s >> 1) & 7) << 11) + (s & 1);
}

// ---------------- Morton cell id + histogram (launch #1) --------------------
__global__ void cell_kernel(const float* __restrict__ pos) {
    int i = blockIdx.x * 256 + threadIdx.x;
    if (i < N_PTS) {
        float x = pos[3*i], y = pos[3*i+1], z = pos[3*i+2];
        int cx = min(GRID_C-1, max(0, (int)((x + 5.0f) * 0.8f)));
        int cy = min(GRID_C-1, max(0, (int)((y + 5.0f) * 0.8f)));
        int cz = min(GRID_C-1, max(0, (int)((z + 5.0f) * 0.8f)));
        int c = 0;
#pragma unroll
        for (int b = 0; b < 3; b++) {
            c |= ((cx >> b) & 1) << (3*b + 2);
            c |= ((cy >> b) & 1) << (3*b + 1);
            c |= ((cz >> b) & 1) << (3*b + 0);
        }
        g_cell[i] = c;
        atomicAdd(&g_cnt[c], 1);
    }
}

// ---------------- scan of 512 cell counts -> g_cur; re-zero g_cnt (#2) ------
__global__ void scan_kernel() {
    __shared__ int ws[16];
    int t = threadIdx.x;           // 512 threads, 1 cell each
    int lane = t & 31, wid = t >> 5;
    int s = g_cnt[t];
    g_cnt[t] = 0;                  // clean histogram for the NEXT graph replay
    int inc = s;
#pragma unroll
    for (int o = 1; o < 32; o <<= 1) {
        int v = __shfl_up_sync(0xFFFFFFFFu, inc, o);
        if (lane >= o) inc += v;
    }
    if (lane == 31) ws[wid] = inc;
    __syncthreads();
    if (t < 16) {
        int v = ws[t], iv = v;
#pragma unroll
        for (int o = 1; o < 16; o <<= 1) {
            int u = __shfl_up_sync(0xFFFFu, iv, o);
            if (t >= o) iv += u;
        }
        ws[t] = iv - v;            // exclusive warp base
    }
    __syncthreads();
    g_cur[t] = ws[wid] + inc - s;  // exclusive prefix
}

// ---------------- scatter coords+ids into Morton-sorted order (#3) ----------
__global__ void scatter_kernel(const float* __restrict__ pos) {
    int i = blockIdx.x * 256 + threadIdx.x;
    if (i < N_PTS) {
        int c = g_cell[i];
        int d = atomicAdd(&g_cur[c], 1);
        g_rx[d] = pos[3*i]; g_ry[d] = pos[3*i+1]; g_rz[d] = pos[3*i+2];
        g_rid16[d] = (unsigned short)i;
    }
}

// ---------------- FPS (#4 -> profiled by the harness ncu capture) -----------
// R13 update path (packed f32x2, conflict-free paired layout, register
// payloads, per-warp prune with stage-1 skip) with a ONE-barrier skeleton:
// every warp's lane0 publishes its cached warp-max key via a single smem
// ATOMS.MAX.64 into s_key[it&3] (active warps refresh via the 5-step shfl
// butterfly first; inactive warps re-contribute the register-cached wrk).
// t0 resets s_key[(it+2)&3] before the barrier: that buffer's last readers
// finished before BAR_{it-1}, its next atomics start after BAR_{it+1}, and
// BAR.SYNC drains the reset STS in between -> race-free with 4 buffers.
// Winner is read post-barrier as an LDS broadcast.
// Key = (md_bits<<32)|((16383-orig)<<14 | s): max md, tie -> min original
// index == jnp.argmax; atomicMax is order-invariant -> deterministic.
// Prune skips only provable fminf no-ops (margins >> fp32 rounding).
__global__ __launch_bounds__(1024, 1)
void fps_kernel(const float* __restrict__ pos) {
    extern __shared__ float sm[];
    float* px = sm;
    float* py = sm + N_PTS;
    float* pz = sm + 2*N_PTS;
    __shared__ unsigned long long s_key[4];

    int t = threadIdx.x, lane = t & 31;
    for (int i = t; i < N_PTS; i += 1024) {
        int a = phys_f32(i);
        px[a] = g_rx[i]; py[a] = g_ry[i]; pz[a] = g_rz[i];
    }
    if (t < 4) s_key[t] = 0ull;
    __syncthreads();

    float md[16];
    unsigned pay[16];
    float lox = FLT_MAX_C, hix = -FLT_MAX_C;
    float loy = FLT_MAX_C, hiy = -FLT_MAX_C;
    float loz = FLT_MAX_C, hiz = -FLT_MAX_C;
#pragma unroll
    for (int j = 0; j < 16; j++) {
        int s = t*16 + j;
        int a = phys_f32(s);
        float x = px[a], y = py[a], z = pz[a];
        lox = fminf(lox, x); hix = fmaxf(hix, x);
        loy = fminf(loy, y); hiy = fmaxf(hiy, y);
        loz = fminf(loz, z); hiz = fmaxf(hiz, z);
        md[j] = FLT_MAX_C;
        pay[j] = ((unsigned)(16383 - (int)g_rid16[s]) << 14) | (unsigned)s;
    }
    if (t == 0) g_idx[0] = 0;
    float lx = pos[0], ly = pos[1], lz = pos[2];   // original point 0

    unsigned long long ck  = 0x7F7FFFFF00000000ull; // thread key (tmax=FLT_MAX)
    unsigned long long wrk = 0;                     // warp-reduced key cache

    const unsigned long long* px2 = (const unsigned long long*)px;
    const unsigned long long* py2 = (const unsigned long long*)py;
    const unsigned long long* pz2 = (const unsigned long long*)pz;

    for (int it = 1; it < M_PTS; ++it) {
        // lx,ly,lz = winner of it-1 (it=1: point 0)
        float tmax = __uint_as_float((unsigned)(ck >> 32));
        float lbx = fmaxf(fmaxf(lox - lx, lx - hix), 0.0f);
        float lby = fmaxf(fmaxf(loy - ly, ly - hiy), 0.0f);
        float lbz = fmaxf(fmaxf(loz - lz, lz - hiz), 0.0f);
        float lb2 = lbx*lbx + lby*lby + lbz*lbz;
        bool act = !(lb2 * 0.999f >= tmax * 1.0001f + 1e-8f);
        if (__ballot_sync(0xFFFFFFFFu, act)) {
            unsigned long long lx2, ly2, lz2;
            unsigned lxb = __float_as_uint(lx), lyb = __float_as_uint(ly),
                     lzb = __float_as_uint(lz);
            PACK2(lx2, lxb, lxb); PACK2(ly2, lyb, lyb); PACK2(lz2, lzb, lzb);
            unsigned long long nk = 0;
#pragma unroll
            for (int p = 0; p < 8; p++) {
                unsigned long long X = px2[t + (p << 10)];
                unsigned long long Y = py2[t + (p << 10)];
                unsigned long long Z = pz2[t + (p << 10)];
                unsigned long long dx, dy, dz, sx, sy, sz, s0, dd;
                SUB2(dx, X, lx2); SUB2(dy, Y, ly2); SUB2(dz, Z, lz2);
                MUL2(sx, dx, dx); MUL2(sy, dy, dy); MUL2(sz, dz, dz);
                ADD2(s0, sx, sy); ADD2(dd, s0, sz);
                unsigned dlo, dhi; UNPACK2(dlo, dhi, dd);
                float m0 = fminf(md[2*p],     __uint_as_float(dlo));
                float m1 = fminf(md[2*p + 1], __uint_as_float(dhi));
                md[2*p] = m0; md[2*p + 1] = m1;
                unsigned long long k0 = ((unsigned long long)__float_as_uint(m0) << 32)
                                      | pay[2*p];
                nk = (k0 > nk) ? k0 : nk;
                unsigned long long k1 = ((unsigned long long)__float_as_uint(m1) << 32)
                                      | pay[2*p + 1];
                nk = (k1 > nk) ? k1 : nk;
            }
            ck = nk;
            wrk = shflmax64(ck);     // refresh warp cache (stage-1)
        }
        // every warp contributes its (possibly cached) warp max: one ATOMS
        if (lane == 0) atomicMax(&s_key[it & 3], wrk);
        if (t == 0) s_key[(it + 2) & 3] = 0ull;   // reset future buffer (drains at BAR)
        __syncthreads();
        unsigned long long w = s_key[it & 3];      // LDS broadcast of the winner
        int sp = (int)(w & 0x3FFF);                // winner's sorted position
        int a = phys_f32(sp);
        lx = px[a]; ly = py[a]; lz = pz[a];
        if (t == 0) g_idx[it] = 16383 - (int)((w >> 14) & 0x3FFF);
    }
}

// ---------------- ||pos||^2 (#5; only knn consumes g_sn) --------------------
__global__ void sn_kernel(const float* __restrict__ pos) {
    int i = blockIdx.x * 256 + threadIdx.x;
    if (i < N_PTS) {
        float x = pos[3*i], y = pos[3*i+1], z = pos[3*i+2];
        g_sn[i] = __fadd_rn(__fadd_rn(__fmul_rn(x,x), __fmul_rn(y,y)), __fmul_rn(z,z));
    }
}

// ---------------- gather: x_s, pos_s (+sumsq), write pos_s to output --------
__global__ void gather_kernel(const float* __restrict__ pos, const float* __restrict__ x,
                              float* __restrict__ out) {
    int gid = blockIdx.x * 256 + threadIdx.x;   // 0 .. M*64-1
    int m = gid >> 6, c = gid & 63;
    int i = g_idx[m];
    g_xs[gid] = x[i*64 + c];
    if (c == 0) {
        float a = pos[3*i], b = pos[3*i+1], d = pos[3*i+2];
        float s = __fadd_rn(__fadd_rn(__fmul_rn(a,a), __fmul_rn(b,b)), __fmul_rn(d,d));
        g_ps[m] = make_float4(a, b, d, s);
        out[262144 + m*3 + 0] = a;
        out[262144 + m*3 + 1] = b;
        out[262144 + m*3 + 2] = d;
    }
}

// ---------------- h-MLP on sampled points: delta = h(x_s)  [M,3] ------------
__global__ void h_kernel(const float* __restrict__ w1, const float* __restrict__ b1,
                         const float* __restrict__ w2, const float* __restrict__ b2) {
    __shared__ float xr[64];
    __shared__ float hid[64];
    int m = blockIdx.x, c = threadIdx.x;
    xr[c] = g_xs[m*64 + c];
    __syncthreads();
    float h = b1[c];
#pragma unroll 8
    for (int k = 0; k < 64; k++) h = fmaf(xr[k], w1[k*64 + c], h);
    hid[c] = fmaxf(h, 0.0f);
    __syncthreads();
    if (c < 3) {
        float o = b2[c];
#pragma unroll 8
        for (int k = 0; k < 64; k++) o = fmaf(hid[k], w2[k*3 + c], o);
        g_delta[m*3 + c] = o;
    }
}

// ---------------- u = x @ f_w1[3:,:] + f_b1   [N,64] (pre-ReLU) -------------
__global__ void u_kernel(const float* __restrict__ x, const float* __restrict__ fw1,
                         const float* __restrict__ fb1) {
    __shared__ float xr[64];
    int n = blockIdx.x, c = threadIdx.x;
    xr[c] = x[n*64 + c];
    __syncthreads();
    float h = fb1[c];
#pragma unroll 8
    for (int k = 0; k < 64; k++) h = fmaf(xr[k], fw1[(3 + k)*64 + c], h);
    g_u[n*64 + c] = h;
}

// ---------------- KNN: per query scan 4096, stable top-16 -------------------
__global__ void knn_kernel(const float* __restrict__ pos, float* __restrict__ out) {
    extern __shared__ float4 sp[];
    int tid = threadIdx.x;
    for (int i = tid; i < M_PTS; i += 128) sp[i] = g_ps[i];
    __syncthreads();
    int n = blockIdx.x * 128 + tid;
    float qx = pos[3*n], qy = pos[3*n+1], qz = pos[3*n+2];
    float s_n = g_sn[n];
    float bd[KNN_K]; int bi[KNN_K];
#pragma unroll
    for (int j = 0; j < KNN_K; j++) { bd[j] = FLT_MAX_C; bi[j] = 0x7FFFFFFF; }
    float worst = FLT_MAX_C;
    for (int m = 0; m < M_PTS; m++) {
        float4 q = sp[m];
        float dot = __fmaf_rn(qz, q.z, __fmaf_rn(qy, q.y, __fmul_rn(qx, q.x)));
        float d2 = __fsub_rn(__fadd_rn(s_n, q.w), __fmul_rn(2.0f, dot));
        if (d2 < worst) {                   // strict: equal d2 -> earlier index kept
            float v = d2; int id = m;
#pragma unroll
            for (int j = 0; j < KNN_K; j++) {
                if (v < bd[j]) {
                    float tv = bd[j]; bd[j] = v;  v = tv;
                    int   ti = bi[j]; bi[j] = id; id = ti;
                }
            }
            worst = bd[KNN_K-1];
        }
    }
    float* osrc = out + 274432;
    float* otgt = out + 536576;
#pragma unroll
    for (int j = 0; j < KNN_K; j++) {
        g_nbr[n*KNN_K + j] = bi[j];
        osrc[n*KNN_K + j] = (float)n;
        otgt[n*KNN_K + j] = (float)bi[j];
    }
}

// ---------------- zero the aggregation buffer -------------------------------
__global__ void zero_aggr_kernel() {
    g_aggr[blockIdx.x * 256 + threadIdx.x] = 0u;
}

// ---------------- per-edge layer-1: hidden = relu(u[src] + a @ W3) ----------
__global__ void hidden_kernel(const float* __restrict__ pos, const float* __restrict__ fw1) {
    __shared__ float w3[192];
    __shared__ float av[4][3];
    int tid = threadIdx.x;                 // 256
    if (tid < 192) w3[tid] = fw1[tid];     // rows 0..2 of f_w1
    int gid = blockIdx.x * 256 + tid;
    int e = gid >> 6, c = gid & 63;
    int eg = tid >> 6;
    int n = e >> 4;
    int m = g_nbr[e];
    if (c < 3) {
        float pcomp = pos[3*n + c];
        float qcomp = ((const float*)&g_ps[m])[c];
        av[eg][c] = __fadd_rn(__fsub_rn(pcomp, qcomp), g_delta[m*3 + c]);
    }
    __syncthreads();
    float h = g_u[n*64 + c];
    h = fmaf(av[eg][0], w3[c],       h);
    h = fmaf(av[eg][1], w3[64 + c],  h);
    h = fmaf(av[eg][2], w3[128 + c], h);
    g_hidden[gid] = fmaxf(h, 0.0f);
}

// ---------------- per-edge layer-2 GEMM + atomicMax aggregation -------------
__global__ __launch_bounds__(128)
void msg_kernel(const float* __restrict__ fw2, const float* __restrict__ fb2) {
    __shared__ float w2s[64*64];
    __shared__ float ht[32*65];           // padded to kill bank conflicts
    __shared__ int   tg[32];
    int tid = threadIdx.x;
    for (int i = tid; i < 4096; i += 128) w2s[i] = fw2[i];
    int e0 = blockIdx.x * 32;
    for (int i = tid; i < 2048; i += 128) {
        ht[(i >> 6)*65 + (i & 63)] = g_hidden[e0*64 + i];
    }
    if (tid < 32) tg[tid] = g_nbr[e0 + tid];
    __syncthreads();

    int te = (tid >> 4) * 4;              // edge base within tile
    int td = (tid & 15) * 4;              // output-dim base
    float acc[4][4];
    float b0 = fb2[td], b1 = fb2[td+1], b2v = fb2[td+2], b3 = fb2[td+3];
#pragma unroll
    for (int i = 0; i < 4; i++) { acc[i][0]=b0; acc[i][1]=b1; acc[i][2]=b2v; acc[i][3]=b3; }

#pragma unroll 4
    for (int k = 0; k < 64; k++) {
        float4 w = *(const float4*)&w2s[k*64 + td];
#pragma unroll
        for (int i = 0; i < 4; i++) {
            float hv = ht[(te + i)*65 + k];
            acc[i][0] = fmaf(hv, w.x, acc[i][0]);
            acc[i][1] = fmaf(hv, w.y, acc[i][1]);
            acc[i][2] = fmaf(hv, w.z, acc[i][2]);
            acc[i][3] = fmaf(hv, w.w, acc[i][3]);
        }
    }
#pragma unroll
    for (int i = 0; i < 4; i++) {
        unsigned* base = &g_aggr[tg[te + i]*64 + td];
        atomicMax(base + 0, encf(acc[i][0]));
        atomicMax(base + 1, encf(acc[i][1]));
        atomicMax(base + 2, encf(acc[i][2]));
        atomicMax(base + 3, encf(acc[i][3]));
    }
}

// ---------------- g-MLP + residual -> x_new (written as f32) ----------------
__global__ void out_kernel(const float* __restrict__ w1, const float* __restrict__ b1,
                           const float* __restrict__ w2, const float* __restrict__ b2,
                           float* __restrict__ out) {
    __shared__ float in[128];
    __shared__ float hid[64];
    int m = blockIdx.x, c = threadIdx.x;
    float xs = g_xs[m*64 + c];
    in[c] = xs;
    unsigned u = g_aggr[m*64 + c];
    in[64 + c] = (u == 0u) ? 0.0f : decf(u);   // isfinite-else-0 rule
    __syncthreads();
    float h = b1[c];
#pragma unroll 8
    for (int k = 0; k < 128; k++) h = fmaf(in[k], w1[k*64 + c], h);
    hid[c] = fmaxf(h, 0.0f);
    __syncthreads();
    float o = b2[c];
#pragma unroll 8
    for (int k = 0; k < 64; k++) o = fmaf(hid[k], w2[k*64 + c], o);
    out[m*64 + c] = xs + o;
}

// ---------------- launcher --------------------------------------------------
extern "C" void kernel_launch(void* const* d_in, const int* in_sizes, int n_in,
                              void* d_out, int out_size) {
    const float* x    = (const float*)d_in[0];
    const float* pos  = (const float*)d_in[1];
    // d_in[2] = edge_index (int64) -- unused by the reference math
    const float* h_w1 = (const float*)d_in[3];
    const float* h_b1 = (const float*)d_in[4];
    const float* h_w2 = (const float*)d_in[5];
    const float* h_b2 = (const float*)d_in[6];
    const float* f_w1 = (const float*)d_in[7];
    const float* f_b1 = (const float*)d_in[8];
    const float* f_w2 = (const float*)d_in[9];
    const float* f_b2 = (const float*)d_in[10];
    const float* g_w1 = (const float*)d_in[11];
    const float* g_b1 = (const float*)d_in[12];
    const float* g_w2 = (const float*)d_in[13];
    const float* g_b2 = (const float*)d_in[14];
    float* out = (float*)d_out;

    size_t fps_smem = (size_t)(3*N_PTS)*sizeof(float);          // 192 KB
    cudaFuncSetAttribute(fps_kernel, cudaFuncAttributeMaxDynamicSharedMemorySize, (int)fps_smem);
    cudaFuncSetAttribute(knn_kernel, cudaFuncAttributeMaxDynamicSharedMemorySize, M_PTS*16);

    // fps_kernel stays the 4th launch so the harness ncu capture profiles it.
    cell_kernel<<<(N_PTS + 255)/256, 256>>>(pos);       // g_cnt zeroed at load / by scan
    scan_kernel<<<1, NCELL>>>();                        // also re-zeroes g_cnt
    scatter_kernel<<<(N_PTS + 255)/256, 256>>>(pos);
    fps_kernel<<<1, 1024, fps_smem>>>(pos);
    sn_kernel<<<(N_PTS + 255)/256, 256>>>(pos);
    gather_kernel<<<(M_PTS*EMB)/256, 256>>>(pos, x, out);
    h_kernel<<<M_PTS, 64>>>(h_w1, h_b1, h_w2, h_b2);
    u_kernel<<<N_PTS, 64>>>(x, f_w1, f_b1);
    zero_aggr_kernel<<<(M_PTS*EMB)/256, 256>>>();
    knn_kernel<<<N_PTS/128, 128, M_PTS*16>>>(pos, out);
    hidden_kernel<<<(NEDGE*EMB)/256, 256>>>(pos, f_w1);
    msg_kernel<<<NEDGE/32, 128>>>(f_w2, f_b2);
    out_kernel<<<M_PTS, 64>>>(g_w1, g_b1, g_w2, g_b2, out);
}

// round 15
// speedup vs baseline: 1.0273x; 1.0273x over previous
#include <cuda_runtime.h>
#include <cstdint>

#define N_PTS 16384
#define M_PTS 4096
#define KNN_K 16
#define EMB   64
#define NEDGE (N_PTS*KNN_K)   // 262144
#define FLT_MAX_C 3.402823466e+38f

#define GRID_C 8              // 8x8x8 = 512 cells
#define NCELL  (GRID_C*GRID_C*GRID_C)

// ---------------- device scratch (static globals: allocation-free) ----------
__device__ int      g_idx[M_PTS];
__device__ float4   g_ps[M_PTS];          // sampled pos: x,y,z, sumsq
__device__ float    g_xs[M_PTS*EMB];      // gathered features
__device__ float    g_delta[M_PTS*3];     // h-MLP output per sampled point
__device__ float    g_sn[N_PTS];          // ||pos||^2 per point
__device__ int      g_nbr[NEDGE];         // knn neighbor ids
__device__ unsigned g_aggr[M_PTS*EMB];    // encoded float max accumulators

// spatial-sort scratch for FPS  (g_cnt zero-initialized at load; scan_kernel
// re-zeroes it after use so every graph replay sees a clean histogram)
__device__ int            g_cnt[NCELL];
__device__ int            g_cur[NCELL];
__device__ int            g_cell[N_PTS];
__device__ float          g_rx[N_PTS], g_ry[N_PTS], g_rz[N_PTS];  // sorted coords
__device__ unsigned short g_rid16[N_PTS]; // sorted order -> original index

// order-preserving float<->uint encoding for atomicMax
__device__ __forceinline__ unsigned encf(float f) {
    unsigned u = __float_as_uint(f);
    return (u & 0x80000000u) ? ~u : (u | 0x80000000u);
}
__device__ __forceinline__ float decf(unsigned u) {
    return (u & 0x80000000u) ? __uint_as_float(u & 0x7FFFFFFFu) : __uint_as_float(~u);
}

// u64 max via shuffle butterfly (all lanes end with the max)
__device__ __forceinline__ unsigned long long shflmax64(unsigned long long k) {
#pragma unroll
    for (int o = 16; o; o >>= 1) {
        unsigned long long k2 = __shfl_xor_sync(0xFFFFFFFFu, k, o);
        k = (k2 > k) ? k2 : k;
    }
    return k;
}

// packed f32x2 ops (two independent IEEE-rn fp32 ops per instruction; each
// half rounds bit-identically to the scalar op)
#define SUB2(out, a, b) asm("sub.rn.f32x2 %0, %1, %2;" : "=l"(out) : "l"(a), "l"(b))
#define MUL2(out, a, b) asm("mul.rn.f32x2 %0, %1, %2;" : "=l"(out) : "l"(a), "l"(b))
#define ADD2(out, a, b) asm("add.rn.f32x2 %0, %1, %2;" : "=l"(out) : "l"(a), "l"(b))
#define PACK2(out, lo, hi) asm("mov.b64 %0, {%1, %2};" : "=l"(out) : "r"(lo), "r"(hi))
#define UNPACK2(lo, hi, in) asm("mov.b64 {%0, %1}, %2;" : "=r"(lo), "=r"(hi) : "l"(in))

// paired smem layout: sorted point s lives at float-addr
//   2*(s>>4) + ((s>>1)&7)*2048 + (s&1)
// so thread t's pair p (points 16t+2p, 16t+2p+1) is ONE u64 at index t+p*1024
// (lane-consecutive -> conflict-free LDS.64).
__device__ __forceinline__ int phys_f32(int s) {
    return ((s >> 4) << 1) + (((s >> 1) & 7) << 11) + (s & 1);
}

// ---------------- Morton cell id + histogram (launch #1) --------------------
__global__ void cell_kernel(const float* __restrict__ pos) {
    int i = blockIdx.x * 256 + threadIdx.x;
    if (i < N_PTS) {
        float x = pos[3*i], y = pos[3*i+1], z = pos[3*i+2];
        int cx = min(GRID_C-1, max(0, (int)((x + 5.0f) * 0.8f)));
        int cy = min(GRID_C-1, max(0, (int)((y + 5.0f) * 0.8f)));
        int cz = min(GRID_C-1, max(0, (int)((z + 5.0f) * 0.8f)));
        int c = 0;
#pragma unroll
        for (int b = 0; b < 3; b++) {
            c |= ((cx >> b) & 1) << (3*b + 2);
            c |= ((cy >> b) & 1) << (3*b + 1);
            c |= ((cz >> b) & 1) << (3*b + 0);
        }
        g_cell[i] = c;
        atomicAdd(&g_cnt[c], 1);
    }
}

// ---------------- scan of 512 cell counts -> g_cur; re-zero g_cnt (#2) ------
__global__ void scan_kernel() {
    __shared__ int ws[16];
    int t = threadIdx.x;           // 512 threads, 1 cell each
    int lane = t & 31, wid = t >> 5;
    int s = g_cnt[t];
    g_cnt[t] = 0;                  // clean histogram for the NEXT graph replay
    int inc = s;
#pragma unroll
    for (int o = 1; o < 32; o <<= 1) {
        int v = __shfl_up_sync(0xFFFFFFFFu, inc, o);
        if (lane >= o) inc += v;
    }
    if (lane == 31) ws[wid] = inc;
    __syncthreads();
    if (t < 16) {
        int v = ws[t], iv = v;
#pragma unroll
        for (int o = 1; o < 16; o <<= 1) {
            int u = __shfl_up_sync(0xFFFFu, iv, o);
            if (t >= o) iv += u;
        }
        ws[t] = iv - v;            // exclusive warp base
    }
    __syncthreads();
    g_cur[t] = ws[wid] + inc - s;  // exclusive prefix
}

// ---------------- scatter coords+ids into Morton-sorted order (#3) ----------
__global__ void scatter_kernel(const float* __restrict__ pos) {
    int i = blockIdx.x * 256 + threadIdx.x;
    if (i < N_PTS) {
        int c = g_cell[i];
        int d = atomicAdd(&g_cur[c], 1);
        g_rx[d] = pos[3*i]; g_ry[d] = pos[3*i+1]; g_rz[d] = pos[3*i+2];
        g_rid16[d] = (unsigned short)i;
    }
}

// ---------------- FPS (#4 -> profiled by the harness ncu capture) -----------
// R13 verbatim (measured best): two barriers, stage-1 skip for pruned warps,
// warp-0-only stage-2, shfl butterflies, packed-f32x2 update loop.
// Key = (md_bits<<32)|((16383-orig)<<14 | s): max md, tie -> min original
// index == jnp.argmax, order-invariant w.r.t. the nondeterministic scatter.
// Prune skips only provable fminf no-ops (margins >> fp32 rounding).
__global__ __launch_bounds__(1024, 1)
void fps_kernel(const float* __restrict__ pos) {
    extern __shared__ float sm[];
    float* px = sm;
    float* py = sm + N_PTS;
    float* pz = sm + 2*N_PTS;
    __shared__ unsigned long long wk[32];
    __shared__ unsigned long long s_win;

    int t = threadIdx.x, lane = t & 31, wid = t >> 5;
    for (int i = t; i < N_PTS; i += 1024) {
        int a = phys_f32(i);
        px[a] = g_rx[i]; py[a] = g_ry[i]; pz[a] = g_rz[i];
    }
    __syncthreads();

    float md[16];
    unsigned pay[16];
    float lox = FLT_MAX_C, hix = -FLT_MAX_C;
    float loy = FLT_MAX_C, hiy = -FLT_MAX_C;
    float loz = FLT_MAX_C, hiz = -FLT_MAX_C;
#pragma unroll
    for (int j = 0; j < 16; j++) {
        int s = t*16 + j;
        int a = phys_f32(s);
        float x = px[a], y = py[a], z = pz[a];
        lox = fminf(lox, x); hix = fmaxf(hix, x);
        loy = fminf(loy, y); hiy = fmaxf(hiy, y);
        loz = fminf(loz, z); hiz = fmaxf(hiz, z);
        md[j] = FLT_MAX_C;
        pay[j] = ((unsigned)(16383 - (int)g_rid16[s]) << 14) | (unsigned)s;
    }
    if (t == 0) g_idx[0] = 0;
    float lx = pos[0], ly = pos[1], lz = pos[2];   // original point 0

    unsigned long long ck = 0x7F7FFFFF00000000ull; // tmax=FLT_MAX -> first iter active

    const unsigned long long* px2 = (const unsigned long long*)px;
    const unsigned long long* py2 = (const unsigned long long*)py;
    const unsigned long long* pz2 = (const unsigned long long*)pz;

    for (int it = 1; it < M_PTS; ++it) {
        float tmax = __uint_as_float((unsigned)(ck >> 32));
        float lbx = fmaxf(fmaxf(lox - lx, lx - hix), 0.0f);
        float lby = fmaxf(fmaxf(loy - ly, ly - hiy), 0.0f);
        float lbz = fmaxf(fmaxf(loz - lz, lz - hiz), 0.0f);
        float lb2 = lbx*lbx + lby*lby + lbz*lbz;
        bool act = !(lb2 * 0.999f >= tmax * 1.0001f + 1e-8f);
        if (__ballot_sync(0xFFFFFFFFu, act)) {
            unsigned long long lx2, ly2, lz2;
            unsigned lxb = __float_as_uint(lx), lyb = __float_as_uint(ly),
                     lzb = __float_as_uint(lz);
            PACK2(lx2, lxb, lxb); PACK2(ly2, lyb, lyb); PACK2(lz2, lzb, lzb);
            unsigned long long nk = 0;
#pragma unroll
            for (int p = 0; p < 8; p++) {
                unsigned long long X = px2[t + (p << 10)];
                unsigned long long Y = py2[t + (p << 10)];
                unsigned long long Z = pz2[t + (p << 10)];
                unsigned long long dx, dy, dz, sx, sy, sz, s0, dd;
                SUB2(dx, X, lx2); SUB2(dy, Y, ly2); SUB2(dz, Z, lz2);
                MUL2(sx, dx, dx); MUL2(sy, dy, dy); MUL2(sz, dz, dz);
                ADD2(s0, sx, sy); ADD2(dd, s0, sz);
                unsigned dlo, dhi; UNPACK2(dlo, dhi, dd);
                float m0 = fminf(md[2*p],     __uint_as_float(dlo));
                float m1 = fminf(md[2*p + 1], __uint_as_float(dhi));
                md[2*p] = m0; md[2*p + 1] = m1;
                unsigned long long k0 = ((unsigned long long)__float_as_uint(m0) << 32)
                                      | pay[2*p];
                nk = (k0 > nk) ? k0 : nk;
                unsigned long long k1 = ((unsigned long long)__float_as_uint(m1) << 32)
                                      | pay[2*p + 1];
                nk = (k1 > nk) ? k1 : nk;
            }
            ck = nk;
            // stage 1 only for warps whose keys could have changed
            unsigned long long k = shflmax64(ck);
            if (lane == 0) wk[wid] = k;
        }
        __syncthreads();
        // stage 2: warp 0 reduces the 32 warp keys
        if (t < 32) {
            unsigned long long k = shflmax64(wk[t]);
            if (t == 0) s_win = k;
        }
        __syncthreads();
        unsigned long long w = s_win;
        int sp = (int)(w & 0x3FFF);                 // winner's sorted position
        int a = phys_f32(sp);
        lx = px[a]; ly = py[a]; lz = pz[a];
        if (t == 0) g_idx[it] = 16383 - (int)((w >> 14) & 0x3FFF);
    }
}

// ---------------- ||pos||^2 (#5; only knn consumes g_sn) --------------------
__global__ void sn_kernel(const float* __restrict__ pos) {
    int i = blockIdx.x * 256 + threadIdx.x;
    if (i < N_PTS) {
        float x = pos[3*i], y = pos[3*i+1], z = pos[3*i+2];
        g_sn[i] = __fadd_rn(__fadd_rn(__fmul_rn(x,x), __fmul_rn(y,y)), __fmul_rn(z,z));
    }
}

// ---------------- gather: x_s, pos_s (+sumsq), write pos_s to output --------
__global__ void gather_kernel(const float* __restrict__ pos, const float* __restrict__ x,
                              float* __restrict__ out) {
    int gid = blockIdx.x * 256 + threadIdx.x;   // 0 .. M*64-1
    int m = gid >> 6, c = gid & 63;
    int i = g_idx[m];
    g_xs[gid] = x[i*64 + c];
    if (c == 0) {
        float a = pos[3*i], b = pos[3*i+1], d = pos[3*i+2];
        float s = __fadd_rn(__fadd_rn(__fmul_rn(a,a), __fmul_rn(b,b)), __fmul_rn(d,d));
        g_ps[m] = make_float4(a, b, d, s);
        out[262144 + m*3 + 0] = a;
        out[262144 + m*3 + 1] = b;
        out[262144 + m*3 + 2] = d;
    }
}

// ---------------- h-MLP on sampled points: delta = h(x_s)  [M,3] ------------
__global__ void h_kernel(const float* __restrict__ w1, const float* __restrict__ b1,
                         const float* __restrict__ w2, const float* __restrict__ b2) {
    __shared__ float xr[64];
    __shared__ float hid[64];
    int m = blockIdx.x, c = threadIdx.x;
    xr[c] = g_xs[m*64 + c];
    __syncthreads();
    float h = b1[c];
#pragma unroll 8
    for (int k = 0; k < 64; k++) h = fmaf(xr[k], w1[k*64 + c], h);
    hid[c] = fmaxf(h, 0.0f);
    __syncthreads();
    if (c < 3) {
        float o = b2[c];
#pragma unroll 8
        for (int k = 0; k < 64; k++) o = fmaf(hid[k], w2[k*3 + c], o);
        g_delta[m*3 + c] = o;
    }
}

// ---------------- KNN: per query scan 4096, stable top-16 -------------------
__global__ void knn_kernel(const float* __restrict__ pos, float* __restrict__ out) {
    extern __shared__ float4 sp[];
    int tid = threadIdx.x;
    for (int i = tid; i < M_PTS; i += 128) sp[i] = g_ps[i];
    __syncthreads();
    int n = blockIdx.x * 128 + tid;
    float qx = pos[3*n], qy = pos[3*n+1], qz = pos[3*n+2];
    float s_n = g_sn[n];
    float bd[KNN_K]; int bi[KNN_K];
#pragma unroll
    for (int j = 0; j < KNN_K; j++) { bd[j] = FLT_MAX_C; bi[j] = 0x7FFFFFFF; }
    float worst = FLT_MAX_C;
    for (int m = 0; m < M_PTS; m++) {
        float4 q = sp[m];
        float dot = __fmaf_rn(qz, q.z, __fmaf_rn(qy, q.y, __fmul_rn(qx, q.x)));
        float d2 = __fsub_rn(__fadd_rn(s_n, q.w), __fmul_rn(2.0f, dot));
        if (d2 < worst) {                   // strict: equal d2 -> earlier index kept
            float v = d2; int id = m;
#pragma unroll
            for (int j = 0; j < KNN_K; j++) {
                if (v < bd[j]) {
                    float tv = bd[j]; bd[j] = v;  v = tv;
                    int   ti = bi[j]; bi[j] = id; id = ti;
                }
            }
            worst = bd[KNN_K-1];
        }
    }
    float* osrc = out + 274432;
    float* otgt = out + 536576;
#pragma unroll
    for (int j = 0; j < KNN_K; j++) {
        g_nbr[n*KNN_K + j] = bi[j];
        osrc[n*KNN_K + j] = (float)n;
        otgt[n*KNN_K + j] = (float)bi[j];
    }
}

// ---------------- zero the aggregation buffer -------------------------------
__global__ void zero_aggr_kernel() {
    g_aggr[blockIdx.x * 256 + threadIdx.x] = 0u;
}

// ---------------- FUSED per-edge MLP: u + hidden + layer-2 + aggregation ----
// 32 edges/block spanning exactly 2 source nodes (n = e>>4). Recomputes
// u = fb1 + sum_k x[n,k]*fw1[3+k,:] (ascending k, identical order to the old
// u_kernel), av = (pos - ps) + delta (identical), hidden = relu(u + av@w3)
// (av0,av1,av2 order, identical), then the unchanged layer-2 tile GEMM +
// atomicMax. Eliminates g_u / g_hidden (2x ~67MB DRAM round-trips) and two
// kernel launches; every accumulation order preserved -> bit-identical.
__global__ __launch_bounds__(128)
void msg_kernel(const float* __restrict__ pos, const float* __restrict__ x,
                const float* __restrict__ fw1, const float* __restrict__ fb1,
                const float* __restrict__ fw2, const float* __restrict__ fb2) {
    __shared__ float w2s[64*64];
    __shared__ float ht[32*65];           // padded to kill bank conflicts
    __shared__ int   tg[32];
    __shared__ float w3[192];
    __shared__ float xr[2][64];
    __shared__ float u2[2][64];
    __shared__ float av[32][3];
    int tid = threadIdx.x;
    int e0 = blockIdx.x * 32;
    int n0 = e0 >> 4;                     // first of the two source nodes

    for (int i = tid; i < 4096; i += 128) w2s[i] = fw2[i];
    for (int i = tid; i < 192; i += 128) w3[i] = fw1[i];   // rows 0..2 of f_w1
    xr[tid >> 6][tid & 63] = x[(n0 + (tid >> 6))*64 + (tid & 63)];
    if (tid < 32) tg[tid] = g_nbr[e0 + tid];
    __syncthreads();

    // u for the 2 source nodes (pre-ReLU), identical op order to old u_kernel
    {
        int i = tid >> 6, c = tid & 63;
        float h = fb1[c];
#pragma unroll 8
        for (int k = 0; k < 64; k++) h = fmaf(xr[i][k], fw1[(3 + k)*64 + c], h);
        u2[i][c] = h;
    }
    // av = (pos - ps) + delta per edge (3 comps), identical to old hidden_kernel
    {
        int le = tid >> 2, c = tid & 3;
        if (c < 3) {
            int m = tg[le];
            int n = n0 + (le >> 4);
            float pcomp = pos[3*n + c];
            float qcomp = ((const float*)&g_ps[m])[c];
            av[le][c] = __fadd_rn(__fsub_rn(pcomp, qcomp), g_delta[m*3 + c]);
        }
    }
    __syncthreads();

    // hidden = relu(u + av@w3) -> smem tile (identical op order)
#pragma unroll
    for (int i = 0; i < 16; i++) {
        int v = tid + i*128;
        int le = v >> 6, c = v & 63;
        float h = u2[le >> 4][c];
        h = fmaf(av[le][0], w3[c],       h);
        h = fmaf(av[le][1], w3[64 + c],  h);
        h = fmaf(av[le][2], w3[128 + c], h);
        ht[le*65 + c] = fmaxf(h, 0.0f);
    }
    __syncthreads();

    // layer-2 tile GEMM + atomicMax aggregation (unchanged)
    int te = (tid >> 4) * 4;              // edge base within tile
    int td = (tid & 15) * 4;              // output-dim base
    float acc[4][4];
    float b0 = fb2[td], b1 = fb2[td+1], b2v = fb2[td+2], b3 = fb2[td+3];
#pragma unroll
    for (int i = 0; i < 4; i++) { acc[i][0]=b0; acc[i][1]=b1; acc[i][2]=b2v; acc[i][3]=b3; }

#pragma unroll 4
    for (int k = 0; k < 64; k++) {
        float4 w = *(const float4*)&w2s[k*64 + td];
#pragma unroll
        for (int i = 0; i < 4; i++) {
            float hv = ht[(te + i)*65 + k];
            acc[i][0] = fmaf(hv, w.x, acc[i][0]);
            acc[i][1] = fmaf(hv, w.y, acc[i][1]);
            acc[i][2] = fmaf(hv, w.z, acc[i][2]);
            acc[i][3] = fmaf(hv, w.w, acc[i][3]);
        }
    }
#pragma unroll
    for (int i = 0; i < 4; i++) {
        unsigned* base = &g_aggr[tg[te + i]*64 + td];
        atomicMax(base + 0, encf(acc[i][0]));
        atomicMax(base + 1, encf(acc[i][1]));
        atomicMax(base + 2, encf(acc[i][2]));
        atomicMax(base + 3, encf(acc[i][3]));
    }
}

// ---------------- g-MLP + residual -> x_new (written as f32) ----------------
__global__ void out_kernel(const float* __restrict__ w1, const float* __restrict__ b1,
                           const float* __restrict__ w2, const float* __restrict__ b2,
                           float* __restrict__ out) {
    __shared__ float in[128];
    __shared__ float hid[64];
    int m = blockIdx.x, c = threadIdx.x;
    float xs = g_xs[m*64 + c];
    in[c] = xs;
    unsigned u = g_aggr[m*64 + c];
    in[64 + c] = (u == 0u) ? 0.0f : decf(u);   // isfinite-else-0 rule
    __syncthreads();
    float h = b1[c];
#pragma unroll 8
    for (int k = 0; k < 128; k++) h = fmaf(in[k], w1[k*64 + c], h);
    hid[c] = fmaxf(h, 0.0f);
    __syncthreads();
    float o = b2[c];
#pragma unroll 8
    for (int k = 0; k < 64; k++) o = fmaf(hid[k], w2[k*64 + c], o);
    out[m*64 + c] = xs + o;
}

// ---------------- launcher --------------------------------------------------
extern "C" void kernel_launch(void* const* d_in, const int* in_sizes, int n_in,
                              void* d_out, int out_size) {
    const float* x    = (const float*)d_in[0];
    const float* pos  = (const float*)d_in[1];
    // d_in[2] = edge_index (int64) -- unused by the reference math
    const float* h_w1 = (const float*)d_in[3];
    const float* h_b1 = (const float*)d_in[4];
    const float* h_w2 = (const float*)d_in[5];
    const float* h_b2 = (const float*)d_in[6];
    const float* f_w1 = (const float*)d_in[7];
    const float* f_b1 = (const float*)d_in[8];
    const float* f_w2 = (const float*)d_in[9];
    const float* f_b2 = (const float*)d_in[10];
    const float* g_w1 = (const float*)d_in[11];
    const float* g_b1 = (const float*)d_in[12];
    const float* g_w2 = (const float*)d_in[13];
    const float* g_b2 = (const float*)d_in[14];
    float* out = (float*)d_out;

    size_t fps_smem = (size_t)(3*N_PTS)*sizeof(float);          // 192 KB
    cudaFuncSetAttribute(fps_kernel, cudaFuncAttributeMaxDynamicSharedMemorySize, (int)fps_smem);
    cudaFuncSetAttribute(knn_kernel, cudaFuncAttributeMaxDynamicSharedMemorySize, M_PTS*16);

    // fps_kernel stays the 4th launch so the harness ncu capture profiles it.
    cell_kernel<<<(N_PTS + 255)/256, 256>>>(pos);       // g_cnt zeroed at load / by scan
    scan_kernel<<<1, NCELL>>>();                        // also re-zeroes g_cnt
    scatter_kernel<<<(N_PTS + 255)/256, 256>>>(pos);
    fps_kernel<<<1, 1024, fps_smem>>>(pos);
    sn_kernel<<<(N_PTS + 255)/256, 256>>>(pos);
    gather_kernel<<<(M_PTS*EMB)/256, 256>>>(pos, x, out);
    h_kernel<<<M_PTS, 64>>>(h_w1, h_b1, h_w2, h_b2);
    zero_aggr_kernel<<<(M_PTS*EMB)/256, 256>>>();
    knn_kernel<<<N_PTS/128, 128, M_PTS*16>>>(pos, out);
    msg_kernel<<<NEDGE/32, 128>>>(pos, x, f_w1, f_b1, f_w2, f_b2);
    out_kernel<<<M_PTS, 64>>>(g_w1, g_b1, g_w2, g_b2, out);
}

// round 16
// speedup vs baseline: 1.2040x; 1.1720x over previous
#include <cuda_runtime.h>
#include <cstdint>

#define N_PTS 16384
#define M_PTS 4096
#define KNN_K 16
#define EMB   64
#define NEDGE (N_PTS*KNN_K)   // 262144
#define FLT_MAX_C 3.402823466e+38f

#define GRID_C 8              // 8x8x8 = 512 cells
#define NCELL  (GRID_C*GRID_C*GRID_C)

// ---------------- device scratch (static globals: allocation-free) ----------
__device__ int      g_idx[M_PTS];
__device__ float4   g_ps[M_PTS];          // sampled pos: x,y,z, sumsq
__device__ float    g_xs[M_PTS*EMB];      // gathered features
__device__ float    g_delta[M_PTS*3];     // h-MLP output per sampled point
__device__ float    g_sn[N_PTS];          // ||pos||^2 per point
__device__ int      g_nbr[NEDGE];         // knn neighbor ids
__device__ unsigned g_aggr[M_PTS*EMB];    // encoded float max accumulators

// spatial-sort scratch for FPS  (g_cnt zero-initialized at load; scan_kernel
// re-zeroes it after use so every graph replay sees a clean histogram)
__device__ int            g_cnt[NCELL];
__device__ int            g_cur[NCELL];
__device__ int            g_cell[N_PTS];
__device__ float          g_rx[N_PTS], g_ry[N_PTS], g_rz[N_PTS];  // sorted coords
__device__ unsigned short g_rid16[N_PTS]; // sorted order -> original index

// order-preserving float<->uint encoding for atomicMax
__device__ __forceinline__ unsigned encf(float f) {
    unsigned u = __float_as_uint(f);
    return (u & 0x80000000u) ? ~u : (u | 0x80000000u);
}
__device__ __forceinline__ float decf(unsigned u) {
    return (u & 0x80000000u) ? __uint_as_float(u & 0x7FFFFFFFu) : __uint_as_float(~u);
}

// warp-wide u64 key max via 2-phase REDUX.SYNC: max over hi-32 (md bits),
// then max payload among holders of that max (non-holders contribute 0;
// a genuine 0 payload is the unique candidate (orig=16383, s=0) and decodes
// correctly). Payload's orig field dominates -> identical tie semantics to
// the u64 butterfly (max md, tie -> min original index == jnp.argmax).
__device__ __forceinline__ unsigned long long redmax64(unsigned long long k) {
    unsigned hi = (unsigned)(k >> 32);
    unsigned h  = __reduce_max_sync(0xFFFFFFFFu, hi);
    unsigned pc = (hi == h) ? (unsigned)k : 0u;
    unsigned p  = __reduce_max_sync(0xFFFFFFFFu, pc);
    return ((unsigned long long)h << 32) | p;
}

// packed f32x2 ops (two independent IEEE-rn fp32 ops per instruction; each
// half rounds bit-identically to the scalar op)
#define SUB2(out, a, b) asm("sub.rn.f32x2 %0, %1, %2;" : "=l"(out) : "l"(a), "l"(b))
#define MUL2(out, a, b) asm("mul.rn.f32x2 %0, %1, %2;" : "=l"(out) : "l"(a), "l"(b))
#define ADD2(out, a, b) asm("add.rn.f32x2 %0, %1, %2;" : "=l"(out) : "l"(a), "l"(b))
#define PACK2(out, lo, hi) asm("mov.b64 %0, {%1, %2};" : "=l"(out) : "r"(lo), "r"(hi))
#define UNPACK2(lo, hi, in) asm("mov.b64 {%0, %1}, %2;" : "=r"(lo), "=r"(hi) : "l"(in))

// paired smem layout: sorted point s lives at float-addr
//   2*(s>>4) + ((s>>1)&7)*2048 + (s&1)
// so thread t's pair p (points 16t+2p, 16t+2p+1) is ONE u64 at index t+p*1024
// (lane-consecutive -> conflict-free LDS.64).
__device__ __forceinline__ int phys_f32(int s) {
    return ((s >> 4) << 1) + (((s >> 1) & 7) << 11) + (s & 1);
}

// ---------------- Morton cell id + histogram + ||pos||^2 (launch #1) --------
__global__ void cell_kernel(const float* __restrict__ pos) {
    int i = blockIdx.x * 256 + threadIdx.x;
    if (i < N_PTS) {
        float x = pos[3*i], y = pos[3*i+1], z = pos[3*i+2];
        g_sn[i] = __fadd_rn(__fadd_rn(__fmul_rn(x,x), __fmul_rn(y,y)), __fmul_rn(z,z));
        int cx = min(GRID_C-1, max(0, (int)((x + 5.0f) * 0.8f)));
        int cy = min(GRID_C-1, max(0, (int)((y + 5.0f) * 0.8f)));
        int cz = min(GRID_C-1, max(0, (int)((z + 5.0f) * 0.8f)));
        int c = 0;
#pragma unroll
        for (int b = 0; b < 3; b++) {
            c |= ((cx >> b) & 1) << (3*b + 2);
            c |= ((cy >> b) & 1) << (3*b + 1);
            c |= ((cz >> b) & 1) << (3*b + 0);
        }
        g_cell[i] = c;
        atomicAdd(&g_cnt[c], 1);
    }
}

// ---------------- scan of 512 cell counts -> g_cur; re-zero g_cnt (#2) ------
__global__ void scan_kernel() {
    __shared__ int ws[16];
    int t = threadIdx.x;           // 512 threads, 1 cell each
    int lane = t & 31, wid = t >> 5;
    int s = g_cnt[t];
    g_cnt[t] = 0;                  // clean histogram for the NEXT graph replay
    int inc = s;
#pragma unroll
    for (int o = 1; o < 32; o <<= 1) {
        int v = __shfl_up_sync(0xFFFFFFFFu, inc, o);
        if (lane >= o) inc += v;
    }
    if (lane == 31) ws[wid] = inc;
    __syncthreads();
    if (t < 16) {
        int v = ws[t], iv = v;
#pragma unroll
        for (int o = 1; o < 16; o <<= 1) {
            int u = __shfl_up_sync(0xFFFFu, iv, o);
            if (t >= o) iv += u;
        }
        ws[t] = iv - v;            // exclusive warp base
    }
    __syncthreads();
    g_cur[t] = ws[wid] + inc - s;  // exclusive prefix
}

// ---------------- scatter coords+ids into Morton-sorted order (#3) ----------
__global__ void scatter_kernel(const float* __restrict__ pos) {
    int i = blockIdx.x * 256 + threadIdx.x;
    if (i < N_PTS) {
        int c = g_cell[i];
        int d = atomicAdd(&g_cur[c], 1);
        g_rx[d] = pos[3*i]; g_ry[d] = pos[3*i+1]; g_rz[d] = pos[3*i+2];
        g_rid16[d] = (unsigned short)i;
    }
}

// ---------------- FPS (#4 -> profiled by the harness ncu capture) -----------
// R13/R15 skeleton verbatim (two barriers, stage-1 skip for pruned warps,
// warp-0-only stage-2, packed-f32x2 update loop); ONLY change: both 5-step
// u64 shuffle butterflies replaced by 2-phase REDUX.SYNC (redmax64), which
// has identical max/tie semantics (see redmax64 comment).
// Key = (md_bits<<32)|((16383-orig)<<14 | s): max md, tie -> min original
// index == jnp.argmax, order-invariant w.r.t. the nondeterministic scatter.
// Prune skips only provable fminf no-ops (margins >> fp32 rounding).
__global__ __launch_bounds__(1024, 1)
void fps_kernel(const float* __restrict__ pos) {
    extern __shared__ float sm[];
    float* px = sm;
    float* py = sm + N_PTS;
    float* pz = sm + 2*N_PTS;
    __shared__ unsigned long long wk[32];
    __shared__ unsigned long long s_win;

    int t = threadIdx.x, lane = t & 31, wid = t >> 5;
    for (int i = t; i < N_PTS; i += 1024) {
        int a = phys_f32(i);
        px[a] = g_rx[i]; py[a] = g_ry[i]; pz[a] = g_rz[i];
    }
    __syncthreads();

    float md[16];
    unsigned pay[16];
    float lox = FLT_MAX_C, hix = -FLT_MAX_C;
    float loy = FLT_MAX_C, hiy = -FLT_MAX_C;
    float loz = FLT_MAX_C, hiz = -FLT_MAX_C;
#pragma unroll
    for (int j = 0; j < 16; j++) {
        int s = t*16 + j;
        int a = phys_f32(s);
        float x = px[a], y = py[a], z = pz[a];
        lox = fminf(lox, x); hix = fmaxf(hix, x);
        loy = fminf(loy, y); hiy = fmaxf(hiy, y);
        loz = fminf(loz, z); hiz = fmaxf(hiz, z);
        md[j] = FLT_MAX_C;
        pay[j] = ((unsigned)(16383 - (int)g_rid16[s]) << 14) | (unsigned)s;
    }
    if (t == 0) g_idx[0] = 0;
    float lx = pos[0], ly = pos[1], lz = pos[2];   // original point 0

    unsigned long long ck = 0x7F7FFFFF00000000ull; // tmax=FLT_MAX -> first iter active

    const unsigned long long* px2 = (const unsigned long long*)px;
    const unsigned long long* py2 = (const unsigned long long*)py;
    const unsigned long long* pz2 = (const unsigned long long*)pz;

    for (int it = 1; it < M_PTS; ++it) {
        float tmax = __uint_as_float((unsigned)(ck >> 32));
        float lbx = fmaxf(fmaxf(lox - lx, lx - hix), 0.0f);
        float lby = fmaxf(fmaxf(loy - ly, ly - hiy), 0.0f);
        float lbz = fmaxf(fmaxf(loz - lz, lz - hiz), 0.0f);
        float lb2 = lbx*lbx + lby*lby + lbz*lbz;
        bool act = !(lb2 * 0.999f >= tmax * 1.0001f + 1e-8f);
        if (__ballot_sync(0xFFFFFFFFu, act)) {
            unsigned long long lx2, ly2, lz2;
            unsigned lxb = __float_as_uint(lx), lyb = __float_as_uint(ly),
                     lzb = __float_as_uint(lz);
            PACK2(lx2, lxb, lxb); PACK2(ly2, lyb, lyb); PACK2(lz2, lzb, lzb);
            unsigned long long nk = 0;
#pragma unroll
            for (int p = 0; p < 8; p++) {
                unsigned long long X = px2[t + (p << 10)];
                unsigned long long Y = py2[t + (p << 10)];
                unsigned long long Z = pz2[t + (p << 10)];
                unsigned long long dx, dy, dz, sx, sy, sz, s0, dd;
                SUB2(dx, X, lx2); SUB2(dy, Y, ly2); SUB2(dz, Z, lz2);
                MUL2(sx, dx, dx); MUL2(sy, dy, dy); MUL2(sz, dz, dz);
                ADD2(s0, sx, sy); ADD2(dd, s0, sz);
                unsigned dlo, dhi; UNPACK2(dlo, dhi, dd);
                float m0 = fminf(md[2*p],     __uint_as_float(dlo));
                float m1 = fminf(md[2*p + 1], __uint_as_float(dhi));
                md[2*p] = m0; md[2*p + 1] = m1;
                unsigned long long k0 = ((unsigned long long)__float_as_uint(m0) << 32)
                                      | pay[2*p];
                nk = (k0 > nk) ? k0 : nk;
                unsigned long long k1 = ((unsigned long long)__float_as_uint(m1) << 32)
                                      | pay[2*p + 1];
                nk = (k1 > nk) ? k1 : nk;
            }
            ck = nk;
            // stage 1 only for warps whose keys could have changed
            unsigned long long k = redmax64(ck);
            if (lane == 0) wk[wid] = k;
        }
        __syncthreads();
        // stage 2: warp 0 reduces the 32 warp keys
        if (t < 32) {
            unsigned long long k = redmax64(wk[t]);
            if (t == 0) s_win = k;
        }
        __syncthreads();
        unsigned long long w = s_win;
        int sp = (int)(w & 0x3FFF);                 // winner's sorted position
        int a = phys_f32(sp);
        lx = px[a]; ly = py[a]; lz = pz[a];
        if (t == 0) g_idx[it] = 16383 - (int)((w >> 14) & 0x3FFF);
    }
}

// ---------------- gather: x_s, pos_s (+sumsq), write pos_s to output --------
__global__ void gather_kernel(const float* __restrict__ pos, const float* __restrict__ x,
                              float* __restrict__ out) {
    int gid = blockIdx.x * 256 + threadIdx.x;   // 0 .. M*64-1
    int m = gid >> 6, c = gid & 63;
    int i = g_idx[m];
    g_xs[gid] = x[i*64 + c];
    if (c == 0) {
        float a = pos[3*i], b = pos[3*i+1], d = pos[3*i+2];
        float s = __fadd_rn(__fadd_rn(__fmul_rn(a,a), __fmul_rn(b,b)), __fmul_rn(d,d));
        g_ps[m] = make_float4(a, b, d, s);
        out[262144 + m*3 + 0] = a;
        out[262144 + m*3 + 1] = b;
        out[262144 + m*3 + 2] = d;
    }
}

// ---------------- h-MLP on sampled points: delta = h(x_s)  [M,3] ------------
__global__ void h_kernel(const float* __restrict__ w1, const float* __restrict__ b1,
                         const float* __restrict__ w2, const float* __restrict__ b2) {
    __shared__ float xr[64];
    __shared__ float hid[64];
    int m = blockIdx.x, c = threadIdx.x;
    xr[c] = g_xs[m*64 + c];
    __syncthreads();
    float h = b1[c];
#pragma unroll 8
    for (int k = 0; k < 64; k++) h = fmaf(xr[k], w1[k*64 + c], h);
    hid[c] = fmaxf(h, 0.0f);
    __syncthreads();
    if (c < 3) {
        float o = b2[c];
#pragma unroll 8
        for (int k = 0; k < 64; k++) o = fmaf(hid[k], w2[k*3 + c], o);
        g_delta[m*3 + c] = o;
    }
}

// ---------------- KNN: per query scan 4096, stable top-16 -------------------
__global__ void knn_kernel(const float* __restrict__ pos, float* __restrict__ out) {
    extern __shared__ float4 sp[];
    int tid = threadIdx.x;
    for (int i = tid; i < M_PTS; i += 128) sp[i] = g_ps[i];
    __syncthreads();
    int n = blockIdx.x * 128 + tid;
    float qx = pos[3*n], qy = pos[3*n+1], qz = pos[3*n+2];
    float s_n = g_sn[n];
    float bd[KNN_K]; int bi[KNN_K];
#pragma unroll
    for (int j = 0; j < KNN_K; j++) { bd[j] = FLT_MAX_C; bi[j] = 0x7FFFFFFF; }
    float worst = FLT_MAX_C;
    for (int m = 0; m < M_PTS; m++) {
        float4 q = sp[m];
        float dot = __fmaf_rn(qz, q.z, __fmaf_rn(qy, q.y, __fmul_rn(qx, q.x)));
        float d2 = __fsub_rn(__fadd_rn(s_n, q.w), __fmul_rn(2.0f, dot));
        if (d2 < worst) {                   // strict: equal d2 -> earlier index kept
            float v = d2; int id = m;
#pragma unroll
            for (int j = 0; j < KNN_K; j++) {
                if (v < bd[j]) {
                    float tv = bd[j]; bd[j] = v;  v = tv;
                    int   ti = bi[j]; bi[j] = id; id = ti;
                }
            }
            worst = bd[KNN_K-1];
        }
    }
    float* osrc = out + 274432;
    float* otgt = out + 536576;
#pragma unroll
    for (int j = 0; j < KNN_K; j++) {
        g_nbr[n*KNN_K + j] = bi[j];
        osrc[n*KNN_K + j] = (float)n;
        otgt[n*KNN_K + j] = (float)bi[j];
    }
}

// ---------------- zero the aggregation buffer -------------------------------
__global__ void zero_aggr_kernel() {
    g_aggr[blockIdx.x * 256 + threadIdx.x] = 0u;
}

// ---------------- FUSED per-edge MLP: u + hidden + layer-2 + aggregation ----
// 32 edges/block spanning exactly 2 source nodes (n = e>>4). Recomputes
// u = fb1 + sum_k x[n,k]*fw1[3+k,:] (ascending k), av = (pos - ps) + delta,
// hidden = relu(u + av@w3) (av0,av1,av2 order), then the layer-2 tile GEMM +
// atomicMax. Every accumulation order preserved -> bit-identical.
__global__ __launch_bounds__(128)
void msg_kernel(const float* __restrict__ pos, const float* __restrict__ x,
                const float* __restrict__ fw1, const float* __restrict__ fb1,
                const float* __restrict__ fw2, const float* __restrict__ fb2) {
    __shared__ float w2s[64*64];
    __shared__ float ht[32*65];           // padded to kill bank conflicts
    __shared__ int   tg[32];
    __shared__ float w3[192];
    __shared__ float xr[2][64];
    __shared__ float u2[2][64];
    __shared__ float av[32][3];
    int tid = threadIdx.x;
    int e0 = blockIdx.x * 32;
    int n0 = e0 >> 4;                     // first of the two source nodes

    for (int i = tid; i < 4096; i += 128) w2s[i] = fw2[i];
    for (int i = tid; i < 192; i += 128) w3[i] = fw1[i];   // rows 0..2 of f_w1
    xr[tid >> 6][tid & 63] = x[(n0 + (tid >> 6))*64 + (tid & 63)];
    if (tid < 32) tg[tid] = g_nbr[e0 + tid];
    __syncthreads();

    // u for the 2 source nodes (pre-ReLU), identical op order to old u_kernel
    {
        int i = tid >> 6, c = tid & 63;
        float h = fb1[c];
#pragma unroll 8
        for (int k = 0; k < 64; k++) h = fmaf(xr[i][k], fw1[(3 + k)*64 + c], h);
        u2[i][c] = h;
    }
    // av = (pos - ps) + delta per edge (3 comps)
    {
        int le = tid >> 2, c = tid & 3;
        if (c < 3) {
            int m = tg[le];
            int n = n0 + (le >> 4);
            float pcomp = pos[3*n + c];
            float qcomp = ((const float*)&g_ps[m])[c];
            av[le][c] = __fadd_rn(__fsub_rn(pcomp, qcomp), g_delta[m*3 + c]);
        }
    }
    __syncthreads();

    // hidden = relu(u + av@w3) -> smem tile (identical op order)
#pragma unroll
    for (int i = 0; i < 16; i++) {
        int v = tid + i*128;
        int le = v >> 6, c = v & 63;
        float h = u2[le >> 4][c];
        h = fmaf(av[le][0], w3[c],       h);
        h = fmaf(av[le][1], w3[64 + c],  h);
        h = fmaf(av[le][2], w3[128 + c], h);
        ht[le*65 + c] = fmaxf(h, 0.0f);
    }
    __syncthreads();

    // layer-2 tile GEMM + atomicMax aggregation (unchanged)
    int te = (tid >> 4) * 4;              // edge base within tile
    int td = (tid & 15) * 4;              // output-dim base
    float acc[4][4];
    float b0 = fb2[td], b1 = fb2[td+1], b2v = fb2[td+2], b3 = fb2[td+3];
#pragma unroll
    for (int i = 0; i < 4; i++) { acc[i][0]=b0; acc[i][1]=b1; acc[i][2]=b2v; acc[i][3]=b3; }

#pragma unroll 4
    for (int k = 0; k < 64; k++) {
        float4 w = *(const float4*)&w2s[k*64 + td];
#pragma unroll
        for (int i = 0; i < 4; i++) {
            float hv = ht[(te + i)*65 + k];
            acc[i][0] = fmaf(hv, w.x, acc[i][0]);
            acc[i][1] = fmaf(hv, w.y, acc[i][1]);
            acc[i][2] = fmaf(hv, w.z, acc[i][2]);
            acc[i][3] = fmaf(hv, w.w, acc[i][3]);
        }
    }
#pragma unroll
    for (int i = 0; i < 4; i++) {
        unsigned* base = &g_aggr[tg[te + i]*64 + td];
        atomicMax(base + 0, encf(acc[i][0]));
        atomicMax(base + 1, encf(acc[i][1]));
        atomicMax(base + 2, encf(acc[i][2]));
        atomicMax(base + 3, encf(acc[i][3]));
    }
}

// ---------------- g-MLP + residual -> x_new (written as f32) ----------------
__global__ void out_kernel(const float* __restrict__ w1, const float* __restrict__ b1,
                           const float* __restrict__ w2, const float* __restrict__ b2,
                           float* __restrict__ out) {
    __shared__ float in[128];
    __shared__ float hid[64];
    int m = blockIdx.x, c = threadIdx.x;
    float xs = g_xs[m*64 + c];
    in[c] = xs;
    unsigned u = g_aggr[m*64 + c];
    in[64 + c] = (u == 0u) ? 0.0f : decf(u);   // isfinite-else-0 rule
    __syncthreads();
    float h = b1[c];
#pragma unroll 8
    for (int k = 0; k < 128; k++) h = fmaf(in[k], w1[k*64 + c], h);
    hid[c] = fmaxf(h, 0.0f);
    __syncthreads();
    float o = b2[c];
#pragma unroll 8
    for (int k = 0; k < 64; k++) o = fmaf(hid[k], w2[k*64 + c], o);
    out[m*64 + c] = xs + o;
}

// ---------------- launcher --------------------------------------------------
extern "C" void kernel_launch(void* const* d_in, const int* in_sizes, int n_in,
                              void* d_out, int out_size) {
    const float* x    = (const float*)d_in[0];
    const float* pos  = (const float*)d_in[1];
    // d_in[2] = edge_index (int64) -- unused by the reference math
    const float* h_w1 = (const float*)d_in[3];
    const float* h_b1 = (const float*)d_in[4];
    const float* h_w2 = (const float*)d_in[5];
    const float* h_b2 = (const float*)d_in[6];
    const float* f_w1 = (const float*)d_in[7];
    const float* f_b1 = (const float*)d_in[8];
    const float* f_w2 = (const float*)d_in[9];
    const float* f_b2 = (const float*)d_in[10];
    const float* g_w1 = (const float*)d_in[11];
    const float* g_b1 = (const float*)d_in[12];
    const float* g_w2 = (const float*)d_in[13];
    const float* g_b2 = (const float*)d_in[14];
    float* out = (float*)d_out;

    size_t fps_smem = (size_t)(3*N_PTS)*sizeof(float);          // 192 KB
    cudaFuncSetAttribute(fps_kernel, cudaFuncAttributeMaxDynamicSharedMemorySize, (int)fps_smem);
    cudaFuncSetAttribute(knn_kernel, cudaFuncAttributeMaxDynamicSharedMemorySize, M_PTS*16);

    // fps_kernel stays the 4th launch so the harness ncu capture profiles it.
    cell_kernel<<<(N_PTS + 255)/256, 256>>>(pos);       // + g_sn; g_cnt zeroed by scan
    scan_kernel<<<1, NCELL>>>();                        // also re-zeroes g_cnt
    scatter_kernel<<<(N_PTS + 255)/256, 256>>>(pos);
    fps_kernel<<<1, 1024, fps_smem>>>(pos);
    gather_kernel<<<(M_PTS*EMB)/256, 256>>>(pos, x, out);
    h_kernel<<<M_PTS, 64>>>(h_w1, h_b1, h_w2, h_b2);
    zero_aggr_kernel<<<(M_PTS*EMB)/256, 256>>>();
    knn_kernel<<<N_PTS/128, 128, M_PTS*16>>>(pos, out);
    msg_kernel<<<NEDGE/32, 128>>>(pos, x, f_w1, f_b1, f_w2, f_b2);
    out_kernel<<<M_PTS, 64>>>(g_w1, g_b1, g_w2, g_b2, out);
}

// round 17
// speedup vs baseline: 1.2374x; 1.0277x over previous
#include <cuda_runtime.h>
#include <cstdint>

#define N_PTS 16384
#define M_PTS 4096
#define KNN_K 16
#define EMB   64
#define NEDGE (N_PTS*KNN_K)   // 262144
#define FLT_MAX_C 3.402823466e+38f

#define GRID_C 8              // 8x8x8 = 512 cells
#define NCELL  (GRID_C*GRID_C*GRID_C)

// ---------------- device scratch (static globals: allocation-free) ----------
__device__ int      g_idx[M_PTS];
__device__ float4   g_ps[M_PTS];          // sampled pos: x,y,z, sumsq
__device__ float    g_xs[M_PTS*EMB];      // gathered features
__device__ float    g_delta[M_PTS*3];     // h-MLP output per sampled point
__device__ float    g_sn[N_PTS];          // ||pos||^2 per point
__device__ int      g_nbr[NEDGE];         // knn neighbor ids
__device__ unsigned g_aggr[M_PTS*EMB];    // encoded float max accumulators

// spatial-sort scratch for FPS  (g_cnt zero-initialized at load; scan_kernel
// re-zeroes it after use so every graph replay sees a clean histogram)
__device__ int            g_cnt[NCELL];
__device__ int            g_cur[NCELL];
__device__ int            g_cell[N_PTS];
__device__ float          g_rx[N_PTS], g_ry[N_PTS], g_rz[N_PTS];  // sorted coords
__device__ unsigned short g_rid16[N_PTS]; // sorted order -> original index

// order-preserving float<->uint encoding for atomicMax
__device__ __forceinline__ unsigned encf(float f) {
    unsigned u = __float_as_uint(f);
    return (u & 0x80000000u) ? ~u : (u | 0x80000000u);
}
__device__ __forceinline__ float decf(unsigned u) {
    return (u & 0x80000000u) ? __uint_as_float(u & 0x7FFFFFFFu) : __uint_as_float(~u);
}

// warp-wide u64 key max via 2-phase REDUX.SYNC: max over hi-32 (md bits),
// then max payload among holders of that max (non-holders contribute 0;
// a genuine 0 payload is the unique candidate (orig=16383, s=0) and decodes
// correctly). Payload's orig field dominates -> identical tie semantics to
// the u64 butterfly (max md, tie -> min original index == jnp.argmax).
__device__ __forceinline__ unsigned long long redmax64(unsigned long long k) {
    unsigned hi = (unsigned)(k >> 32);
    unsigned h  = __reduce_max_sync(0xFFFFFFFFu, hi);
    unsigned pc = (hi == h) ? (unsigned)k : 0u;
    unsigned p  = __reduce_max_sync(0xFFFFFFFFu, pc);
    return ((unsigned long long)h << 32) | p;
}

// packed f32x2 ops (two independent IEEE-rn fp32 ops per instruction; each
// half rounds bit-identically to the scalar op)
#define SUB2(out, a, b) asm("sub.rn.f32x2 %0, %1, %2;" : "=l"(out) : "l"(a), "l"(b))
#define MUL2(out, a, b) asm("mul.rn.f32x2 %0, %1, %2;" : "=l"(out) : "l"(a), "l"(b))
#define ADD2(out, a, b) asm("add.rn.f32x2 %0, %1, %2;" : "=l"(out) : "l"(a), "l"(b))
#define PACK2(out, lo, hi) asm("mov.b64 %0, {%1, %2};" : "=l"(out) : "r"(lo), "r"(hi))
#define UNPACK2(lo, hi, in) asm("mov.b64 {%0, %1}, %2;" : "=r"(lo), "=r"(hi) : "l"(in))

// paired smem layout: sorted point s lives at float-addr
//   2*(s>>4) + ((s>>1)&7)*2048 + (s&1)
// so thread t's pair p (points 16t+2p, 16t+2p+1) is ONE u64 at index t+p*1024
// (lane-consecutive -> conflict-free LDS.64).
__device__ __forceinline__ int phys_f32(int s) {
    return ((s >> 4) << 1) + (((s >> 1) & 7) << 11) + (s & 1);
}

// ------ Morton cell id + histogram + ||pos||^2 + zero g_aggr (launch #1) ----
// Grid covers 262144 threads: all zero one g_aggr word; the first 16384 also
// compute sn/cell/histogram. (zero_aggr_kernel folded in; stream order still
// guarantees g_aggr is clean before msg_kernel runs.)
__global__ void cell_kernel(const float* __restrict__ pos) {
    int i = blockIdx.x * 256 + threadIdx.x;
    g_aggr[i] = 0u;                       // grid size == M_PTS*EMB exactly
    if (i < N_PTS) {
        float x = pos[3*i], y = pos[3*i+1], z = pos[3*i+2];
        g_sn[i] = __fadd_rn(__fadd_rn(__fmul_rn(x,x), __fmul_rn(y,y)), __fmul_rn(z,z));
        int cx = min(GRID_C-1, max(0, (int)((x + 5.0f) * 0.8f)));
        int cy = min(GRID_C-1, max(0, (int)((y + 5.0f) * 0.8f)));
        int cz = min(GRID_C-1, max(0, (int)((z + 5.0f) * 0.8f)));
        int c = 0;
#pragma unroll
        for (int b = 0; b < 3; b++) {
            c |= ((cx >> b) & 1) << (3*b + 2);
            c |= ((cy >> b) & 1) << (3*b + 1);
            c |= ((cz >> b) & 1) << (3*b + 0);
        }
        g_cell[i] = c;
        atomicAdd(&g_cnt[c], 1);
    }
}

// ---------------- scan of 512 cell counts -> g_cur; re-zero g_cnt (#2) ------
__global__ void scan_kernel() {
    __shared__ int ws[16];
    int t = threadIdx.x;           // 512 threads, 1 cell each
    int lane = t & 31, wid = t >> 5;
    int s = g_cnt[t];
    g_cnt[t] = 0;                  // clean histogram for the NEXT graph replay
    int inc = s;
#pragma unroll
    for (int o = 1; o < 32; o <<= 1) {
        int v = __shfl_up_sync(0xFFFFFFFFu, inc, o);
        if (lane >= o) inc += v;
    }
    if (lane == 31) ws[wid] = inc;
    __syncthreads();
    if (t < 16) {
        int v = ws[t], iv = v;
#pragma unroll
        for (int o = 1; o < 16; o <<= 1) {
            int u = __shfl_up_sync(0xFFFFu, iv, o);
            if (t >= o) iv += u;
        }
        ws[t] = iv - v;            // exclusive warp base
    }
    __syncthreads();
    g_cur[t] = ws[wid] + inc - s;  // exclusive prefix
}

// ---------------- scatter coords+ids into Morton-sorted order (#3) ----------
__global__ void scatter_kernel(const float* __restrict__ pos) {
    int i = blockIdx.x * 256 + threadIdx.x;
    if (i < N_PTS) {
        int c = g_cell[i];
        int d = atomicAdd(&g_cur[c], 1);
        g_rx[d] = pos[3*i]; g_ry[d] = pos[3*i+1]; g_rz[d] = pos[3*i+2];
        g_rid16[d] = (unsigned short)i;
    }
}

// ---------------- FPS (#4 -> profiled by the harness ncu capture) -----------
// R16 verbatim (measured best): two barriers, stage-1 skip for pruned warps,
// warp-0-only stage-2, 2-phase REDUX.SYNC reductions, packed-f32x2 update.
// Key = (md_bits<<32)|((16383-orig)<<14 | s): max md, tie -> min original
// index == jnp.argmax, order-invariant w.r.t. the nondeterministic scatter.
// Prune skips only provable fminf no-ops (margins >> fp32 rounding).
__global__ __launch_bounds__(1024, 1)
void fps_kernel(const float* __restrict__ pos) {
    extern __shared__ float sm[];
    float* px = sm;
    float* py = sm + N_PTS;
    float* pz = sm + 2*N_PTS;
    __shared__ unsigned long long wk[32];
    __shared__ unsigned long long s_win;

    int t = threadIdx.x, lane = t & 31, wid = t >> 5;
    for (int i = t; i < N_PTS; i += 1024) {
        int a = phys_f32(i);
        px[a] = g_rx[i]; py[a] = g_ry[i]; pz[a] = g_rz[i];
    }
    __syncthreads();

    float md[16];
    unsigned pay[16];
    float lox = FLT_MAX_C, hix = -FLT_MAX_C;
    float loy = FLT_MAX_C, hiy = -FLT_MAX_C;
    float loz = FLT_MAX_C, hiz = -FLT_MAX_C;
#pragma unroll
    for (int j = 0; j < 16; j++) {
        int s = t*16 + j;
        int a = phys_f32(s);
        float x = px[a], y = py[a], z = pz[a];
        lox = fminf(lox, x); hix = fmaxf(hix, x);
        loy = fminf(loy, y); hiy = fmaxf(hiy, y);
        loz = fminf(loz, z); hiz = fmaxf(hiz, z);
        md[j] = FLT_MAX_C;
        pay[j] = ((unsigned)(16383 - (int)g_rid16[s]) << 14) | (unsigned)s;
    }
    if (t == 0) g_idx[0] = 0;
    float lx = pos[0], ly = pos[1], lz = pos[2];   // original point 0

    unsigned long long ck = 0x7F7FFFFF00000000ull; // tmax=FLT_MAX -> first iter active

    const unsigned long long* px2 = (const unsigned long long*)px;
    const unsigned long long* py2 = (const unsigned long long*)py;
    const unsigned long long* pz2 = (const unsigned long long*)pz;

    for (int it = 1; it < M_PTS; ++it) {
        float tmax = __uint_as_float((unsigned)(ck >> 32));
        float lbx = fmaxf(fmaxf(lox - lx, lx - hix), 0.0f);
        float lby = fmaxf(fmaxf(loy - ly, ly - hiy), 0.0f);
        float lbz = fmaxf(fmaxf(loz - lz, lz - hiz), 0.0f);
        float lb2 = lbx*lbx + lby*lby + lbz*lbz;
        bool act = !(lb2 * 0.999f >= tmax * 1.0001f + 1e-8f);
        if (__ballot_sync(0xFFFFFFFFu, act)) {
            unsigned long long lx2, ly2, lz2;
            unsigned lxb = __float_as_uint(lx), lyb = __float_as_uint(ly),
                     lzb = __float_as_uint(lz);
            PACK2(lx2, lxb, lxb); PACK2(ly2, lyb, lyb); PACK2(lz2, lzb, lzb);
            unsigned long long nk = 0;
#pragma unroll
            for (int p = 0; p < 8; p++) {
                unsigned long long X = px2[t + (p << 10)];
                unsigned long long Y = py2[t + (p << 10)];
                unsigned long long Z = pz2[t + (p << 10)];
                unsigned long long dx, dy, dz, sx, sy, sz, s0, dd;
                SUB2(dx, X, lx2); SUB2(dy, Y, ly2); SUB2(dz, Z, lz2);
                MUL2(sx, dx, dx); MUL2(sy, dy, dy); MUL2(sz, dz, dz);
                ADD2(s0, sx, sy); ADD2(dd, s0, sz);
                unsigned dlo, dhi; UNPACK2(dlo, dhi, dd);
                float m0 = fminf(md[2*p],     __uint_as_float(dlo));
                float m1 = fminf(md[2*p + 1], __uint_as_float(dhi));
                md[2*p] = m0; md[2*p + 1] = m1;
                unsigned long long k0 = ((unsigned long long)__float_as_uint(m0) << 32)
                                      | pay[2*p];
                nk = (k0 > nk) ? k0 : nk;
                unsigned long long k1 = ((unsigned long long)__float_as_uint(m1) << 32)
                                      | pay[2*p + 1];
                nk = (k1 > nk) ? k1 : nk;
            }
            ck = nk;
            // stage 1 only for warps whose keys could have changed
            unsigned long long k = redmax64(ck);
            if (lane == 0) wk[wid] = k;
        }
        __syncthreads();
        // stage 2: warp 0 reduces the 32 warp keys
        if (t < 32) {
            unsigned long long k = redmax64(wk[t]);
            if (t == 0) s_win = k;
        }
        __syncthreads();
        unsigned long long w = s_win;
        int sp = (int)(w & 0x3FFF);                 // winner's sorted position
        int a = phys_f32(sp);
        lx = px[a]; ly = py[a]; lz = pz[a];
        if (t == 0) g_idx[it] = 16383 - (int)((w >> 14) & 0x3FFF);
    }
}

// ------- FUSED gather + h-MLP (#5): x_s, pos_s, delta = h(x_s) --------------
// Block m: reads x[g_idx[m]] directly (gather fused), writes g_xs (consumed
// by out_kernel), g_ps (+sumsq, consumed by knn/msg) and the pos_s output;
// then the unchanged h-MLP producing g_delta. Identical op order throughout.
__global__ void h_kernel(const float* __restrict__ pos, const float* __restrict__ x,
                         const float* __restrict__ w1, const float* __restrict__ b1,
                         const float* __restrict__ w2, const float* __restrict__ b2,
                         float* __restrict__ out) {
    __shared__ float xr[64];
    __shared__ float hid[64];
    int m = blockIdx.x, c = threadIdx.x;
    int i = g_idx[m];
    float xs = x[i*64 + c];
    g_xs[m*64 + c] = xs;
    xr[c] = xs;
    if (c == 0) {
        float a = pos[3*i], b = pos[3*i+1], d = pos[3*i+2];
        float s = __fadd_rn(__fadd_rn(__fmul_rn(a,a), __fmul_rn(b,b)), __fmul_rn(d,d));
        g_ps[m] = make_float4(a, b, d, s);
        out[262144 + m*3 + 0] = a;
        out[262144 + m*3 + 1] = b;
        out[262144 + m*3 + 2] = d;
    }
    __syncthreads();
    float h = b1[c];
#pragma unroll 8
    for (int k = 0; k < 64; k++) h = fmaf(xr[k], w1[k*64 + c], h);
    hid[c] = fmaxf(h, 0.0f);
    __syncthreads();
    if (c < 3) {
        float o = b2[c];
#pragma unroll 8
        for (int k = 0; k < 64; k++) o = fmaf(hid[k], w2[k*3 + c], o);
        g_delta[m*3 + c] = o;
    }
}

// ---------------- KNN: per query scan 4096, stable top-16 -------------------
__global__ void knn_kernel(const float* __restrict__ pos, float* __restrict__ out) {
    extern __shared__ float4 sp[];
    int tid = threadIdx.x;
    for (int i = tid; i < M_PTS; i += 128) sp[i] = g_ps[i];
    __syncthreads();
    int n = blockIdx.x * 128 + tid;
    float qx = pos[3*n], qy = pos[3*n+1], qz = pos[3*n+2];
    float s_n = g_sn[n];
    float bd[KNN_K]; int bi[KNN_K];
#pragma unroll
    for (int j = 0; j < KNN_K; j++) { bd[j] = FLT_MAX_C; bi[j] = 0x7FFFFFFF; }
    float worst = FLT_MAX_C;
#pragma unroll 4
    for (int m = 0; m < M_PTS; m++) {
        float4 q = sp[m];
        float dot = __fmaf_rn(qz, q.z, __fmaf_rn(qy, q.y, __fmul_rn(qx, q.x)));
        float d2 = __fsub_rn(__fadd_rn(s_n, q.w), __fmul_rn(2.0f, dot));
        if (d2 < worst) {                   // strict: equal d2 -> earlier index kept
            float v = d2; int id = m;
#pragma unroll
            for (int j = 0; j < KNN_K; j++) {
                if (v < bd[j]) {
                    float tv = bd[j]; bd[j] = v;  v = tv;
                    int   ti = bi[j]; bi[j] = id; id = ti;
                }
            }
            worst = bd[KNN_K-1];
        }
    }
    float* osrc = out + 274432;
    float* otgt = out + 536576;
#pragma unroll
    for (int j = 0; j < KNN_K; j++) {
        g_nbr[n*KNN_K + j] = bi[j];
        osrc[n*KNN_K + j] = (float)n;
        otgt[n*KNN_K + j] = (float)bi[j];
    }
}

// ---------------- FUSED per-edge MLP: u + hidden + layer-2 + aggregation ----
// 32 edges/block spanning exactly 2 source nodes (n = e>>4). Recomputes
// u = fb1 + sum_k x[n,k]*fw1[3+k,:] (ascending k), av = (pos - ps) + delta,
// hidden = relu(u + av@w3) (av0,av1,av2 order), then the layer-2 tile GEMM +
// atomicMax. Every accumulation order preserved -> bit-identical.
__global__ __launch_bounds__(128)
void msg_kernel(const float* __restrict__ pos, const float* __restrict__ x,
                const float* __restrict__ fw1, const float* __restrict__ fb1,
                const float* __restrict__ fw2, const float* __restrict__ fb2) {
    __shared__ float w2s[64*64];
    __shared__ float ht[32*65];           // padded to kill bank conflicts
    __shared__ int   tg[32];
    __shared__ float w3[192];
    __shared__ float xr[2][64];
    __shared__ float u2[2][64];
    __shared__ float av[32][3];
    int tid = threadIdx.x;
    int e0 = blockIdx.x * 32;
    int n0 = e0 >> 4;                     // first of the two source nodes

    // vectorized weight load (1024 float4 = 8 per thread)
    for (int i = tid; i < 1024; i += 128)
        ((float4*)w2s)[i] = ((const float4*)fw2)[i];
    for (int i = tid; i < 192; i += 128) w3[i] = fw1[i];   // rows 0..2 of f_w1
    xr[tid >> 6][tid & 63] = x[(n0 + (tid >> 6))*64 + (tid & 63)];
    if (tid < 32) tg[tid] = g_nbr[e0 + tid];
    __syncthreads();

    // u for the 2 source nodes (pre-ReLU), identical op order to old u_kernel
    {
        int i = tid >> 6, c = tid & 63;
        float h = fb1[c];
#pragma unroll 8
        for (int k = 0; k < 64; k++) h = fmaf(xr[i][k], fw1[(3 + k)*64 + c], h);
        u2[i][c] = h;
    }
    // av = (pos - ps) + delta per edge (3 comps)
    {
        int le = tid >> 2, c = tid & 3;
        if (c < 3) {
            int m = tg[le];
            int n = n0 + (le >> 4);
            float pcomp = pos[3*n + c];
            float qcomp = ((const float*)&g_ps[m])[c];
            av[le][c] = __fadd_rn(__fsub_rn(pcomp, qcomp), g_delta[m*3 + c]);
        }
    }
    __syncthreads();

    // hidden = relu(u + av@w3) -> smem tile (identical op order)
#pragma unroll
    for (int i = 0; i < 16; i++) {
        int v = tid + i*128;
        int le = v >> 6, c = v & 63;
        float h = u2[le >> 4][c];
        h = fmaf(av[le][0], w3[c],       h);
        h = fmaf(av[le][1], w3[64 + c],  h);
        h = fmaf(av[le][2], w3[128 + c], h);
        ht[le*65 + c] = fmaxf(h, 0.0f);
    }
    __syncthreads();

    // layer-2 tile GEMM + atomicMax aggregation (unchanged)
    int te = (tid >> 4) * 4;              // edge base within tile
    int td = (tid & 15) * 4;              // output-dim base
    float acc[4][4];
    float b0 = fb2[td], b1 = fb2[td+1], b2v = fb2[td+2], b3 = fb2[td+3];
#pragma unroll
    for (int i = 0; i < 4; i++) { acc[i][0]=b0; acc[i][1]=b1; acc[i][2]=b2v; acc[i][3]=b3; }

#pragma unroll 4
    for (int k = 0; k < 64; k++) {
        float4 w = *(const float4*)&w2s[k*64 + td];
#pragma unroll
        for (int i = 0; i < 4; i++) {
            float hv = ht[(te + i)*65 + k];
            acc[i][0] = fmaf(hv, w.x, acc[i][0]);
            acc[i][1] = fmaf(hv, w.y, acc[i][1]);
            acc[i][2] = fmaf(hv, w.z, acc[i][2]);
            acc[i][3] = fmaf(hv, w.w, acc[i][3]);
        }
    }
#pragma unroll
    for (int i = 0; i < 4; i++) {
        unsigned* base = &g_aggr[tg[te + i]*64 + td];
        atomicMax(base + 0, encf(acc[i][0]));
        atomicMax(base + 1, encf(acc[i][1]));
        atomicMax(base + 2, encf(acc[i][2]));
        atomicMax(base + 3, encf(acc[i][3]));
    }
}

// ---------------- g-MLP + residual -> x_new (written as f32) ----------------
__global__ void out_kernel(const float* __restrict__ w1, const float* __restrict__ b1,
                           const float* __restrict__ w2, const float* __restrict__ b2,
                           float* __restrict__ out) {
    __shared__ float in[128];
    __shared__ float hid[64];
    int m = blockIdx.x, c = threadIdx.x;
    float xs = g_xs[m*64 + c];
    in[c] = xs;
    unsigned u = g_aggr[m*64 + c];
    in[64 + c] = (u == 0u) ? 0.0f : decf(u);   // isfinite-else-0 rule
    __syncthreads();
    float h = b1[c];
#pragma unroll 8
    for (int k = 0; k < 128; k++) h = fmaf(in[k], w1[k*64 + c], h);
    hid[c] = fmaxf(h, 0.0f);
    __syncthreads();
    float o = b2[c];
#pragma unroll 8
    for (int k = 0; k < 64; k++) o = fmaf(hid[k], w2[k*64 + c], o);
    out[m*64 + c] = xs + o;
}

// ---------------- launcher --------------------------------------------------
extern "C" void kernel_launch(void* const* d_in, const int* in_sizes, int n_in,
                              void* d_out, int out_size) {
    const float* x    = (const float*)d_in[0];
    const float* pos  = (const float*)d_in[1];
    // d_in[2] = edge_index (int64) -- unused by the reference math
    const float* h_w1 = (const float*)d_in[3];
    const float* h_b1 = (const float*)d_in[4];
    const float* h_w2 = (const float*)d_in[5];
    const float* h_b2 = (const float*)d_in[6];
    const float* f_w1 = (const float*)d_in[7];
    const float* f_b1 = (const float*)d_in[8];
    const float* f_w2 = (const float*)d_in[9];
    const float* f_b2 = (const float*)d_in[10];
    const float* g_w1 = (const float*)d_in[11];
    const float* g_b1 = (const float*)d_in[12];
    const float* g_w2 = (const float*)d_in[13];
    const float* g_b2 = (const float*)d_in[14];
    float* out = (float*)d_out;

    size_t fps_smem = (size_t)(3*N_PTS)*sizeof(float);          // 192 KB
    cudaFuncSetAttribute(fps_kernel, cudaFuncAttributeMaxDynamicSharedMemorySize, (int)fps_smem);
    cudaFuncSetAttribute(knn_kernel, cudaFuncAttributeMaxDynamicSharedMemorySize, M_PTS*16);

    // fps_kernel stays the 4th launch so the harness ncu capture profiles it.
    cell_kernel<<<(M_PTS*EMB)/256, 256>>>(pos);     // sn+cell+hist+zero g_aggr
    scan_kernel<<<1, NCELL>>>();                    // also re-zeroes g_cnt
    scatter_kernel<<<(N_PTS + 255)/256, 256>>>(pos);
    fps_kernel<<<1, 1024, fps_smem>>>(pos);
    h_kernel<<<M_PTS, 64>>>(pos, x, h_w1, h_b1, h_w2, h_b2, out);  // + gather
    knn_kernel<<<N_PTS/128, 128, M_PTS*16>>>(pos, out);
    msg_kernel<<<NEDGE/32, 128>>>(pos, x, f_w1, f_b1, f_w2, f_b2);
    out_kernel<<<M_PTS, 64>>>(g_w1, g_b1, g_w2, g_b2, out);
}